// round 3
// baseline (speedup 1.0000x reference)
#include <cuda_runtime.h>

#define NN 200000
#define EE 3200000

// ---- device scratch (no runtime allocation allowed) ----
__device__ int    g_src[EE];
__device__ int    g_dst[EE];
__device__ float  g_nw[EE];
__device__ float  g_deg[NN];          // reused as dinv after k_dinv
__device__ int    g_is64;
__device__ float4 g_h [NN * 8];       // 32 floats per node
__device__ float4 g_a [NN * 8];
__device__ float4 g_t1[NN * 8];
__device__ float4 g_t2[NN * 8];

// ---------------------------------------------------------------- preprocessing

// Detect edge_index dtype. Genuine int64 indices are all < NN; int32 data
// reinterpreted as int64 yields huge values almost surely. All sampled int64
// slots are < 64*997+1 < 3.2M, i.e. within the buffer under EITHER dtype
// (int32 buffer = 25.6MB = 3.2M int64 slots).
__global__ void k_detect(const void* __restrict__ eiraw) {
    const long long* p = (const long long*)eiraw;
    int ok = 1;
    for (int i = 0; i < 64; i++) {
        long long v = p[i * 997 + 1];
        if (v < 0 || v >= NN) { ok = 0; break; }
    }
    g_is64 = ok;
}

__global__ void k_zero_deg() {
    int i = blockIdx.x * 256 + threadIdx.x;
    if (i < NN) g_deg[i] = 0.0f;
}

__global__ void k_prep(const void* __restrict__ eiraw) {
    int e = blockIdx.x * 256 + threadIdx.x;
    if (e >= EE) return;
    int s, d;
    if (g_is64) {
        const long long* p = (const long long*)eiraw;
        s = (int)p[e];
        d = (int)p[EE + e];
    } else {
        const int* p = (const int*)eiraw;
        s = p[e];
        d = p[EE + e];
    }
    if ((unsigned)s >= NN || (unsigned)d >= NN) return;  // never expected; avoids crash
    g_src[e] = s;
    g_dst[e] = d;
    atomicAdd(&g_deg[s], 1.0f);
}

__global__ void k_dinv() {
    int i = blockIdx.x * 256 + threadIdx.x;
    if (i >= NN) return;
    float d = g_deg[i];
    g_deg[i] = (d > 0.0f) ? rsqrtf(d) : 0.0f;   // deg>0 => deg>=1 => max(deg,1)=deg
}

__global__ void k_nw() {
    int e = blockIdx.x * 256 + threadIdx.x;
    if (e >= EE) return;
    g_nw[e] = -g_deg[g_src[e]] * g_deg[g_dst[e]];
}

// ---------------------------------------------------------------- node kernels

// h = relu(x @ W0 + b0), x:[N,3], W0:[3,32]. warp-per-node, lane = out feature.
__global__ void __launch_bounds__(256) k_input(const float* __restrict__ x,
                                               const float* __restrict__ W0,
                                               const float* __restrict__ b0) {
    int tid = blockIdx.x * 256 + threadIdx.x;
    int n = tid >> 5, j = tid & 31;
    if (n >= NN) return;
    float x0 = __ldg(&x[n * 3 + 0]);
    float x1 = __ldg(&x[n * 3 + 1]);
    float x2 = __ldg(&x[n * 3 + 2]);
    float acc = __ldg(&b0[j]);
    acc = fmaf(x0, __ldg(&W0[j]),      acc);
    acc = fmaf(x1, __ldg(&W0[32 + j]), acc);
    acc = fmaf(x2, __ldg(&W0[64 + j]), acc);
    ((float*)g_h)[n * 32 + j] = fmaxf(acc, 0.0f);
}

__global__ void k_zero2(float4* __restrict__ a, float4* __restrict__ b) {
    int i = blockIdx.x * 256 + threadIdx.x;
    if (i >= NN * 8) return;
    float4 z = make_float4(0.f, 0.f, 0.f, 0.f);
    a[i] = z;
    b[i] = z;
}

// ---------------------------------------------------------------- edge propagation

__device__ __forceinline__ void red_add_v4(float4* a, float x, float y, float z, float w) {
    asm volatile("red.global.add.v4.f32 [%0], {%1, %2, %3, %4};"
                 :: "l"(a), "f"(x), "f"(y), "f"(z), "f"(w) : "memory");
}

// y[dst] += nw * x[src], 8 lanes (float4 each) per edge; warp covers 4 edges.
__global__ void __launch_bounds__(256) k_prop(const float4* __restrict__ X,
                                              float4* __restrict__ Y) {
    int u = blockIdx.x * 256 + threadIdx.x;   // EE*8 = 25.6M units
    if (u >= EE * 8) return;
    int e = u >> 3, q = u & 7;
    int s = g_src[e];
    int d = g_dst[e];
    float w = g_nw[e];
    float4 v = __ldg(&X[s * 8 + q]);
    red_add_v4(&Y[d * 8 + q], w * v.x, w * v.y, w * v.z, w * v.w);
}

// ---------------------------------------------------------------- cheb combine

// out = X@W[0] + T1@W[1] + (2*T2 - X)@W[2] + bias [+res] [relu]
__global__ void __launch_bounds__(256) k_combine(const float* __restrict__ X,
                                                 const float* __restrict__ T1,
                                                 const float* __restrict__ T2v,
                                                 const float* __restrict__ W,
                                                 const float* __restrict__ bias,
                                                 const float* __restrict__ res,
                                                 float* __restrict__ out,
                                                 int doRelu) {
    int tid = blockIdx.x * 256 + threadIdx.x;
    int n = tid >> 5, j = tid & 31;
    if (n >= NN) return;
    float xv = X[n * 32 + j];
    float av = T1[n * 32 + j];
    float tv = 2.0f * T2v[n * 32 + j] - xv;
    float acc = __ldg(&bias[j]);
    if (res) acc += res[n * 32 + j];
#pragma unroll
    for (int i = 0; i < 32; i++) {
        float xi = __shfl_sync(0xffffffffu, xv, i);
        float ai = __shfl_sync(0xffffffffu, av, i);
        float ti = __shfl_sync(0xffffffffu, tv, i);
        acc = fmaf(xi, __ldg(&W[i * 32 + j]),        acc);
        acc = fmaf(ai, __ldg(&W[1024 + i * 32 + j]), acc);
        acc = fmaf(ti, __ldg(&W[2048 + i * 32 + j]), acc);
    }
    if (doRelu) acc = fmaxf(acc, 0.0f);
    out[n * 32 + j] = acc;
}

// ---------------------------------------------------------------- output head

__global__ void __launch_bounds__(256) k_final(const float* __restrict__ H,
                                               const float* __restrict__ W1,
                                               const float* __restrict__ b1,
                                               float* __restrict__ out) {
    int tid = blockIdx.x * 256 + threadIdx.x;
    int n = tid >> 5, j = tid & 31;
    if (n >= NN) return;
    float v = H[n * 32 + j] * __ldg(&W1[j]);
#pragma unroll
    for (int o = 16; o; o >>= 1) v += __shfl_down_sync(0xffffffffu, v, o);
    if (j == 0) out[n] = v + __ldg(b1);
}

// ---------------------------------------------------------------- launch

extern "C" void kernel_launch(void* const* d_in, const int* in_sizes, int n_in,
                              void* d_out, int out_size) {
    // ---- resolve inputs by element count (robust to metadata ordering) ----
    // x: 600000, edge_index: 6400000, W0: 96, b1: 1,
    // cheb weights: 3072 x4 (relative order = c11,c12,c21,c22),
    // 32-sized x6: four cheb biases (each immediately follows its 3072 weight),
    // plus b0 and W1. If the two leftovers are adjacent, ordering is
    // alphabetical (W1 before b0); otherwise earlier leftover is b0.
    int idx_x = 0, idx_ei = 1, idx_W0 = 2, idx_b1 = 13;
    int chebW[4] = {4, 6, 8, 10};
    int chebB[4] = {5, 7, 9, 11};
    int idx_b0 = 3, idx_W1 = 12;
    {
        int cw[4], ncw = 0, s32[8], ns = 0;
        int ix = -1, iei = -1, iw0 = -1, ib1 = -1;
        for (int i = 0; i < n_in; i++) {
            int s = in_sizes[i];
            if (s == 600000) ix = i;
            else if (s == 6400000) iei = i;
            else if (s == 96) iw0 = i;
            else if (s == 1) ib1 = i;
            else if (s == 3072 && ncw < 4) cw[ncw++] = i;
            else if (s == 32 && ns < 8) s32[ns++] = i;
        }
        if (ix >= 0 && iei >= 0 && iw0 >= 0 && ib1 >= 0 && ncw == 4 && ns == 6) {
            idx_x = ix; idx_ei = iei; idx_W0 = iw0; idx_b1 = ib1;
            int rem[2], nr = 0;
            for (int k = 0; k < 4; k++) chebW[k] = cw[k];
            for (int i = 0; i < 6; i++) {
                int isb = 0;
                for (int k = 0; k < 4; k++)
                    if (s32[i] == cw[k] + 1) { chebB[k] = s32[i]; isb = 1; }
                if (!isb && nr < 2) rem[nr++] = s32[i];
            }
            if (nr == 2) {
                if (rem[1] == rem[0] + 1) { idx_W1 = rem[0]; idx_b0 = rem[1]; }
                else                      { idx_b0 = rem[0]; idx_W1 = rem[1]; }
            }
        }
    }

    const float* x    = (const float*)d_in[idx_x];
    const void*  ei   = d_in[idx_ei];
    const float* W0   = (const float*)d_in[idx_W0];
    const float* b0   = (const float*)d_in[idx_b0];
    const float* c11W = (const float*)d_in[chebW[0]];
    const float* c11b = (const float*)d_in[chebB[0]];
    const float* c12W = (const float*)d_in[chebW[1]];
    const float* c12b = (const float*)d_in[chebB[1]];
    const float* c21W = (const float*)d_in[chebW[2]];
    const float* c21b = (const float*)d_in[chebB[2]];
    const float* c22W = (const float*)d_in[chebW[3]];
    const float* c22b = (const float*)d_in[chebB[3]];
    const float* W1   = (const float*)d_in[idx_W1];
    const float* b1   = (const float*)d_in[idx_b1];
    float*       out  = (float*)d_out;

    float4 *ph, *pa, *pt1, *pt2;
    cudaGetSymbolAddress((void**)&ph,  g_h);
    cudaGetSymbolAddress((void**)&pa,  g_a);
    cudaGetSymbolAddress((void**)&pt1, g_t1);
    cudaGetSymbolAddress((void**)&pt2, g_t2);

    const int NB_N  = (NN + 255) / 256;
    const int NB_E  = (EE + 255) / 256;
    const int NB_NF = (NN * 32) / 256;      // 25000
    const int NB_Z  = (NN * 8 + 255) / 256;
    const int NB_P  = (EE * 8) / 256;       // 100000

    k_detect<<<1, 1>>>(ei);
    k_zero_deg<<<NB_N, 256>>>();
    k_prep<<<NB_E, 256>>>(ei);
    k_dinv<<<NB_N, 256>>>();
    k_nw<<<NB_E, 256>>>();
    k_input<<<NB_NF, 256>>>(x, W0, b0);

    auto cheb = [&](const float* W, const float* b, float4* Xb,
                    const float4* resb, float4* outb, int relu) {
        k_zero2<<<NB_Z, 256>>>(pt1, pt2);
        k_prop<<<NB_P, 256>>>((const float4*)Xb, pt1);
        k_prop<<<NB_P, 256>>>((const float4*)pt1, pt2);
        k_combine<<<NB_NF, 256>>>((const float*)Xb, (const float*)pt1,
                                  (const float*)pt2, W, b,
                                  (const float*)resb, (float*)outb, relu);
    };

    // block 1: h0=h; h=relu(conv11(h)); h=relu(conv12(h)+h0)
    cheb(c11W, c11b, ph, nullptr, pa, 1);
    cheb(c12W, c12b, pa, ph,      ph, 1);
    // block 2
    cheb(c21W, c21b, ph, nullptr, pa, 1);
    cheb(c22W, c22b, pa, ph,      ph, 1);

    k_final<<<NB_NF, 256>>>((const float*)ph, W1, b1, out);
}

// round 4
// speedup vs baseline: 1.1117x; 1.1117x over previous
#include <cuda_runtime.h>

#define NN 200000
#define EE 3200000

// ---- device scratch (no runtime allocation allowed) ----
__device__ int      g_is64;
__device__ int      g_cnt_src[NN];
__device__ int      g_cnt_dst[NN];
__device__ int      g_fill[NN];
__device__ int      g_rowptr[NN];
__device__ float    g_dinv[NN];
__device__ unsigned g_cursor;
__device__ int2     g_pairs[EE];       // (src, w-bits) grouped contiguously by dst
__device__ float    g_h [NN * 32];
__device__ float    g_a [NN * 32];
__device__ float    g_t1[NN * 32];

// ---------------------------------------------------------------- dtype detect

// Genuine int64 indices are all < NN; int32 data reinterpreted as int64 gives
// huge values almost surely. Sampled slots stay inside the buffer under either
// dtype (int32 buffer = 3.2M int64 slots; max sample 62812).
__global__ void k_detect(const void* __restrict__ eiraw) {
    const long long* p = (const long long*)eiraw;
    int ok = 1;
    for (int i = 0; i < 64; i++) {
        long long v = p[i * 997 + 1];
        if (v < 0 || v >= NN) { ok = 0; break; }
    }
    g_is64 = ok;
}

__device__ __forceinline__ void decode_edge(const void* eiraw, int e, int& s, int& d) {
    if (g_is64) {
        const long long* p = (const long long*)eiraw;
        s = (int)p[e];
        d = (int)p[EE + e];
    } else {
        const int* p = (const int*)eiraw;
        s = p[e];
        d = p[EE + e];
    }
}

// ---------------------------------------------------------------- CSR build

__global__ void k_zero() {
    int i = blockIdx.x * 256 + threadIdx.x;
    if (i < NN) { g_cnt_src[i] = 0; g_cnt_dst[i] = 0; g_fill[i] = 0; }
    if (i == 0) g_cursor = 0u;
}

__global__ void k_count(const void* __restrict__ eiraw) {
    int e = blockIdx.x * 256 + threadIdx.x;
    if (e >= EE) return;
    int s, d;
    decode_edge(eiraw, e, s, d);
    if ((unsigned)s >= NN || (unsigned)d >= NN) return;
    atomicAdd(&g_cnt_src[s], 1);
    atomicAdd(&g_cnt_dst[d], 1);
}

__global__ void k_dinv() {
    int i = blockIdx.x * 256 + threadIdx.x;
    if (i >= NN) return;
    int c = g_cnt_src[i];
    g_dinv[i] = (c > 0) ? rsqrtf((float)c) : 0.0f;
}

// contiguous row regions; placement order irrelevant (per-row sums independent)
__global__ void k_rowalloc() {
    int i = blockIdx.x * 256 + threadIdx.x;
    if (i >= NN) return;
    g_rowptr[i] = (int)atomicAdd(&g_cursor, (unsigned)g_cnt_dst[i]);
}

__global__ void k_fill(const void* __restrict__ eiraw) {
    int e = blockIdx.x * 256 + threadIdx.x;
    if (e >= EE) return;
    int s, d;
    decode_edge(eiraw, e, s, d);
    if ((unsigned)s >= NN || (unsigned)d >= NN) return;
    float w = -g_dinv[s] * g_dinv[d];
    int pos = g_rowptr[d] + atomicAdd(&g_fill[d], 1);
    g_pairs[pos] = make_int2(s, __float_as_int(w));
}

// ---------------------------------------------------------------- input layer

// h = relu(x @ W0 + b0), warp-per-node, lane = out feature.
__global__ void __launch_bounds__(256) k_input(const float* __restrict__ x,
                                               const float* __restrict__ W0,
                                               const float* __restrict__ b0) {
    int tid = blockIdx.x * 256 + threadIdx.x;
    int n = tid >> 5, j = tid & 31;
    if (n >= NN) return;
    float x0 = __ldg(&x[n * 3 + 0]);
    float x1 = __ldg(&x[n * 3 + 1]);
    float x2 = __ldg(&x[n * 3 + 2]);
    float acc = __ldg(&b0[j]);
    acc = fmaf(x0, __ldg(&W0[j]),      acc);
    acc = fmaf(x1, __ldg(&W0[32 + j]), acc);
    acc = fmaf(x2, __ldg(&W0[64 + j]), acc);
    g_h[n * 32 + j] = fmaxf(acc, 0.0f);
}

// ---------------------------------------------------------------- propagation

// y-row accumulation for one node across a warp's 32 lanes.
__device__ __forceinline__ float prop_row(const float* __restrict__ X,
                                          int n, int lane) {
    int beg = g_rowptr[n];
    int end = beg + g_cnt_dst[n];
    float acc = 0.0f;
    for (int base = beg; base < end; base += 32) {
        int nb = end - base; if (nb > 32) nb = 32;
        int2 pr = make_int2(0, 0);
        if (base + lane < end) pr = __ldg(&g_pairs[base + lane]);
        for (int k = 0; k < nb; k++) {
            int   s = __shfl_sync(0xffffffffu, pr.x, k);
            float w = __int_as_float(__shfl_sync(0xffffffffu, pr.y, k));
            acc = fmaf(w, __ldg(&X[s * 32 + lane]), acc);
        }
    }
    return acc;
}

// T1 = L~ X  (first Chebyshev propagation)
__global__ void __launch_bounds__(256) k_prop_csr(const float* __restrict__ X,
                                                  float* __restrict__ Y) {
    int tid = blockIdx.x * 256 + threadIdx.x;
    int n = tid >> 5, lane = tid & 31;
    if (n >= NN) return;
    Y[n * 32 + lane] = prop_row(X, n, lane);
}

// Second propagation fused with combine:
// y = L~ T1 ; T2 = 2y - X ; out = X@W[0] + T1@W[1] + T2@W[2] + b [+res][relu]
__global__ void __launch_bounds__(256) k_prop_combine(const float* __restrict__ X,
                                                      const float* __restrict__ T1,
                                                      const float* __restrict__ W,
                                                      const float* __restrict__ bias,
                                                      const float* __restrict__ res,
                                                      float* __restrict__ out,
                                                      int doRelu) {
    __shared__ float sW[3072];
    __shared__ float sB[32];
    for (int i = threadIdx.x; i < 3072; i += 256) sW[i] = W[i];
    if (threadIdx.x < 32) sB[threadIdx.x] = bias[threadIdx.x];
    __syncthreads();

    int tid = blockIdx.x * 256 + threadIdx.x;
    int n = tid >> 5, lane = tid & 31;
    if (n >= NN) return;

    float yv  = prop_row(T1, n, lane);
    float xv  = X[n * 32 + lane];
    float t1v = T1[n * 32 + lane];
    float t2v = 2.0f * yv - xv;

    float acc = sB[lane];
    if (res) acc += res[n * 32 + lane];
#pragma unroll
    for (int i = 0; i < 32; i++) {
        float xi = __shfl_sync(0xffffffffu, xv, i);
        float ai = __shfl_sync(0xffffffffu, t1v, i);
        float ti = __shfl_sync(0xffffffffu, t2v, i);
        acc = fmaf(xi, sW[i * 32 + lane],        acc);
        acc = fmaf(ai, sW[1024 + i * 32 + lane], acc);
        acc = fmaf(ti, sW[2048 + i * 32 + lane], acc);
    }
    if (doRelu) acc = fmaxf(acc, 0.0f);
    out[n * 32 + lane] = acc;
}

// ---------------------------------------------------------------- output head

__global__ void __launch_bounds__(256) k_final(const float* __restrict__ H,
                                               const float* __restrict__ W1,
                                               const float* __restrict__ b1,
                                               float* __restrict__ out) {
    int tid = blockIdx.x * 256 + threadIdx.x;
    int n = tid >> 5, j = tid & 31;
    if (n >= NN) return;
    float v = H[n * 32 + j] * __ldg(&W1[j]);
#pragma unroll
    for (int o = 16; o; o >>= 1) v += __shfl_down_sync(0xffffffffu, v, o);
    if (j == 0) out[n] = v + __ldg(b1);
}

// ---------------------------------------------------------------- launch

extern "C" void kernel_launch(void* const* d_in, const int* in_sizes, int n_in,
                              void* d_out, int out_size) {
    // ---- resolve inputs by element count (robust to metadata ordering) ----
    int idx_x = 0, idx_ei = 1, idx_W0 = 2, idx_b1 = 13;
    int chebW[4] = {4, 6, 8, 10};
    int chebB[4] = {5, 7, 9, 11};
    int idx_b0 = 3, idx_W1 = 12;
    {
        int cw[4], ncw = 0, s32[8], ns = 0;
        int ix = -1, iei = -1, iw0 = -1, ib1 = -1;
        for (int i = 0; i < n_in; i++) {
            int s = in_sizes[i];
            if (s == 600000) ix = i;
            else if (s == 6400000) iei = i;
            else if (s == 96) iw0 = i;
            else if (s == 1) ib1 = i;
            else if (s == 3072 && ncw < 4) cw[ncw++] = i;
            else if (s == 32 && ns < 8) s32[ns++] = i;
        }
        if (ix >= 0 && iei >= 0 && iw0 >= 0 && ib1 >= 0 && ncw == 4 && ns == 6) {
            idx_x = ix; idx_ei = iei; idx_W0 = iw0; idx_b1 = ib1;
            int rem[2], nr = 0;
            for (int k = 0; k < 4; k++) chebW[k] = cw[k];
            for (int i = 0; i < 6; i++) {
                int isb = 0;
                for (int k = 0; k < 4; k++)
                    if (s32[i] == cw[k] + 1) { chebB[k] = s32[i]; isb = 1; }
                if (!isb && nr < 2) rem[nr++] = s32[i];
            }
            if (nr == 2) {
                if (rem[1] == rem[0] + 1) { idx_W1 = rem[0]; idx_b0 = rem[1]; }
                else                      { idx_b0 = rem[0]; idx_W1 = rem[1]; }
            }
        }
    }

    const float* x    = (const float*)d_in[idx_x];
    const void*  ei   = d_in[idx_ei];
    const float* W0   = (const float*)d_in[idx_W0];
    const float* b0   = (const float*)d_in[idx_b0];
    const float* cW[4], *cB[4];
    for (int k = 0; k < 4; k++) { cW[k] = (const float*)d_in[chebW[k]]; cB[k] = (const float*)d_in[chebB[k]]; }
    const float* W1   = (const float*)d_in[idx_W1];
    const float* b1   = (const float*)d_in[idx_b1];
    float*       out  = (float*)d_out;

    float *ph, *pa, *pt1;
    cudaGetSymbolAddress((void**)&ph,  g_h);
    cudaGetSymbolAddress((void**)&pa,  g_a);
    cudaGetSymbolAddress((void**)&pt1, g_t1);

    const int NB_N  = (NN + 255) / 256;
    const int NB_E  = (EE + 255) / 256;
    const int NB_W  = (NN * 32) / 256;   // warp-per-node kernels: 25000 blocks

    k_detect<<<1, 1>>>(ei);
    k_zero<<<NB_N, 256>>>();
    k_count<<<NB_E, 256>>>(ei);
    k_dinv<<<NB_N, 256>>>();
    k_rowalloc<<<NB_N, 256>>>();
    k_fill<<<NB_E, 256>>>(ei);
    k_input<<<NB_W, 256>>>(x, W0, b0);

    auto cheb = [&](int k, const float* Xb, const float* resb, float* outb) {
        k_prop_csr<<<NB_W, 256>>>(Xb, pt1);
        k_prop_combine<<<NB_W, 256>>>(Xb, pt1, cW[k], cB[k], resb, outb, 1);
    };

    // block 1: h0=h; h=relu(conv11(h)); h=relu(conv12(h)+h0)
    cheb(0, ph, nullptr, pa);
    cheb(1, pa, ph,      ph);
    // block 2
    cheb(2, ph, nullptr, pa);
    cheb(3, pa, ph,      ph);

    k_final<<<NB_W, 256>>>(ph, W1, b1, out);
}

// round 6
// speedup vs baseline: 1.1345x; 1.0205x over previous
#include <cuda_runtime.h>

#define NN 200000
#define EE 3200000

// ---- device scratch (no runtime allocation allowed) ----
__device__ int      g_is64;
__device__ int      g_cnt_src[NN];
__device__ int      g_cnt_dst[NN];
__device__ int      g_fill[NN];
__device__ int      g_rowptr[NN];
__device__ float    g_dinv[NN];
__device__ unsigned g_cursor;
__device__ int2     g_pairs[EE];       // (src, w-bits) grouped contiguously by dst
__device__ float    g_h [NN * 32];
__device__ float    g_a [NN * 32];
__device__ float    g_t1[NN * 32];

// ---------------------------------------------------------------- dtype detect

// Genuine int64 indices are all < NN; int32 data reinterpreted as int64 gives
// huge values almost surely. Sampled slots stay inside the buffer under either
// dtype (int32 buffer = 3.2M int64 slots; max sample 62812).
__global__ void k_detect(const void* __restrict__ eiraw) {
    const long long* p = (const long long*)eiraw;
    int ok = 1;
    for (int i = 0; i < 64; i++) {
        long long v = p[i * 997 + 1];
        if (v < 0 || v >= NN) { ok = 0; break; }
    }
    g_is64 = ok;
}

__device__ __forceinline__ void decode_edge(const void* eiraw, int e, int& s, int& d) {
    if (g_is64) {
        const long long* p = (const long long*)eiraw;
        s = (int)p[e];
        d = (int)p[EE + e];
    } else {
        const int* p = (const int*)eiraw;
        s = p[e];
        d = p[EE + e];
    }
}

// ---------------------------------------------------------------- CSR build

__global__ void k_zero() {
    int i = blockIdx.x * 256 + threadIdx.x;
    if (i < NN) { g_cnt_src[i] = 0; g_cnt_dst[i] = 0; g_fill[i] = 0; }
    if (i == 0) g_cursor = 0u;
}

__global__ void k_count(const void* __restrict__ eiraw) {
    int e = blockIdx.x * 256 + threadIdx.x;
    if (e >= EE) return;
    int s, d;
    decode_edge(eiraw, e, s, d);
    if ((unsigned)s >= NN || (unsigned)d >= NN) return;
    atomicAdd(&g_cnt_src[s], 1);
    atomicAdd(&g_cnt_dst[d], 1);
}

// dinv + contiguous row allocation (placement order irrelevant)
__global__ void k_dinv_rowalloc() {
    int i = blockIdx.x * 256 + threadIdx.x;
    if (i >= NN) return;
    int c = g_cnt_src[i];
    g_dinv[i] = (c > 0) ? rsqrtf((float)c) : 0.0f;
    g_rowptr[i] = (int)atomicAdd(&g_cursor, (unsigned)g_cnt_dst[i]);
}

__global__ void k_fill(const void* __restrict__ eiraw) {
    int e = blockIdx.x * 256 + threadIdx.x;
    if (e >= EE) return;
    int s, d;
    decode_edge(eiraw, e, s, d);
    if ((unsigned)s >= NN || (unsigned)d >= NN) return;
    float w = -g_dinv[s] * g_dinv[d];
    int pos = g_rowptr[d] + atomicAdd(&g_fill[d], 1);
    g_pairs[pos] = make_int2(s, __float_as_int(w));
}

// ---------------------------------------------------------------- input layer

// h = relu(x @ W0 + b0), warp-per-node, lane = out feature.
__global__ void __launch_bounds__(256) k_input(const float* __restrict__ x,
                                               const float* __restrict__ W0,
                                               const float* __restrict__ b0) {
    int tid = blockIdx.x * 256 + threadIdx.x;
    int n = tid >> 5, j = tid & 31;
    if (n >= NN) return;
    float x0 = __ldg(&x[n * 3 + 0]);
    float x1 = __ldg(&x[n * 3 + 1]);
    float x2 = __ldg(&x[n * 3 + 2]);
    float acc = __ldg(&b0[j]);
    acc = fmaf(x0, __ldg(&W0[j]),      acc);
    acc = fmaf(x1, __ldg(&W0[32 + j]), acc);
    acc = fmaf(x2, __ldg(&W0[64 + j]), acc);
    g_h[n * 32 + j] = fmaxf(acc, 0.0f);
}

// ---------------------------------------------------------------- propagation

// y-row accumulation for one node across a warp's 32 lanes.
// Edge records are loaded warp-uniformly (one sector, L1-resident line covers
// 16 records); gather addresses are loop-independent -> MLP via unroll.
__device__ __forceinline__ float prop_row(const float* __restrict__ X,
                                          int n, int lane) {
    int p   = g_rowptr[n];
    int end = p + g_cnt_dst[n];
    float acc = 0.0f;
#pragma unroll 4
    for (; p < end; ++p) {
        int2 pr = __ldg(&g_pairs[p]);                         // uniform per warp
        acc = fmaf(__int_as_float(pr.y),
                   __ldg(&X[pr.x * 32 + lane]), acc);          // coalesced 128B
    }
    return acc;
}

// T1 = L~ X  (first Chebyshev propagation)
__global__ void __launch_bounds__(256) k_prop_csr(const float* __restrict__ X,
                                                  float* __restrict__ Y) {
    int tid = blockIdx.x * 256 + threadIdx.x;
    int n = tid >> 5, lane = tid & 31;
    if (n >= NN) return;
    Y[n * 32 + lane] = prop_row(X, n, lane);
}

// Second propagation fused with combine:
// y = L~ T1 ; T2 = 2y - X ; out = X@W[0] + T1@W[1] + T2@W[2] + b [+res][relu]
__global__ void __launch_bounds__(256) k_prop_combine(const float* __restrict__ X,
                                                      const float* __restrict__ T1,
                                                      const float* __restrict__ W,
                                                      const float* __restrict__ bias,
                                                      const float* __restrict__ res,
                                                      float* __restrict__ out,
                                                      int doRelu) {
    __shared__ float sW[3072];
    __shared__ float sB[32];
    for (int i = threadIdx.x; i < 3072; i += 256) sW[i] = W[i];
    if (threadIdx.x < 32) sB[threadIdx.x] = bias[threadIdx.x];
    __syncthreads();

    int tid = blockIdx.x * 256 + threadIdx.x;
    int n = tid >> 5, lane = tid & 31;
    if (n >= NN) return;

    float yv  = prop_row(T1, n, lane);
    float xv  = X[n * 32 + lane];
    float t1v = T1[n * 32 + lane];
    float t2v = 2.0f * yv - xv;

    float acc = sB[lane];
    if (res) acc += res[n * 32 + lane];
#pragma unroll
    for (int i = 0; i < 32; i++) {
        float xi = __shfl_sync(0xffffffffu, xv, i);
        float ai = __shfl_sync(0xffffffffu, t1v, i);
        float ti = __shfl_sync(0xffffffffu, t2v, i);
        acc = fmaf(xi, sW[i * 32 + lane],        acc);
        acc = fmaf(ai, sW[1024 + i * 32 + lane], acc);
        acc = fmaf(ti, sW[2048 + i * 32 + lane], acc);
    }
    if (doRelu) acc = fmaxf(acc, 0.0f);
    out[n * 32 + lane] = acc;
}

// ---------------------------------------------------------------- output head

__global__ void __launch_bounds__(256) k_final(const float* __restrict__ H,
                                               const float* __restrict__ W1,
                                               const float* __restrict__ b1,
                                               float* __restrict__ out) {
    int tid = blockIdx.x * 256 + threadIdx.x;
    int n = tid >> 5, j = tid & 31;
    if (n >= NN) return;
    float v = H[n * 32 + j] * __ldg(&W1[j]);
#pragma unroll
    for (int o = 16; o; o >>= 1) v += __shfl_down_sync(0xffffffffu, v, o);
    if (j == 0) out[n] = v + __ldg(b1);
}

// ---------------------------------------------------------------- launch

extern "C" void kernel_launch(void* const* d_in, const int* in_sizes, int n_in,
                              void* d_out, int out_size) {
    // ---- resolve inputs by element count (robust to metadata ordering) ----
    int idx_x = 0, idx_ei = 1, idx_W0 = 2, idx_b1 = 13;
    int chebW[4] = {4, 6, 8, 10};
    int chebB[4] = {5, 7, 9, 11};
    int idx_b0 = 3, idx_W1 = 12;
    {
        int cw[4], ncw = 0, s32[8], ns = 0;
        int ix = -1, iei = -1, iw0 = -1, ib1 = -1;
        for (int i = 0; i < n_in; i++) {
            int s = in_sizes[i];
            if (s == 600000) ix = i;
            else if (s == 6400000) iei = i;
            else if (s == 96) iw0 = i;
            else if (s == 1) ib1 = i;
            else if (s == 3072 && ncw < 4) cw[ncw++] = i;
            else if (s == 32 && ns < 8) s32[ns++] = i;
        }
        if (ix >= 0 && iei >= 0 && iw0 >= 0 && ib1 >= 0 && ncw == 4 && ns == 6) {
            idx_x = ix; idx_ei = iei; idx_W0 = iw0; idx_b1 = ib1;
            int rem[2], nr = 0;
            for (int k = 0; k < 4; k++) chebW[k] = cw[k];
            for (int i = 0; i < 6; i++) {
                int isb = 0;
                for (int k = 0; k < 4; k++)
                    if (s32[i] == cw[k] + 1) { chebB[k] = s32[i]; isb = 1; }
                if (!isb && nr < 2) rem[nr++] = s32[i];
            }
            if (nr == 2) {
                if (rem[1] == rem[0] + 1) { idx_W1 = rem[0]; idx_b0 = rem[1]; }
                else                      { idx_b0 = rem[0]; idx_W1 = rem[1]; }
            }
        }
    }

    const float* x    = (const float*)d_in[idx_x];
    const void*  ei   = d_in[idx_ei];
    const float* W0   = (const float*)d_in[idx_W0];
    const float* b0   = (const float*)d_in[idx_b0];
    const float* cW[4], *cB[4];
    for (int k = 0; k < 4; k++) { cW[k] = (const float*)d_in[chebW[k]]; cB[k] = (const float*)d_in[chebB[k]]; }
    const float* W1   = (const float*)d_in[idx_W1];
    const float* b1   = (const float*)d_in[idx_b1];
    float*       out  = (float*)d_out;

    float *ph, *pa, *pt1;
    cudaGetSymbolAddress((void**)&ph,  g_h);
    cudaGetSymbolAddress((void**)&pa,  g_a);
    cudaGetSymbolAddress((void**)&pt1, g_t1);

    const int NB_N  = (NN + 255) / 256;
    const int NB_E  = (EE + 255) / 256;
    const int NB_W  = (NN * 32) / 256;   // warp-per-node kernels: 25000 blocks

    k_detect<<<1, 1>>>(ei);
    k_zero<<<NB_N, 256>>>();
    k_count<<<NB_E, 256>>>(ei);
    k_dinv_rowalloc<<<NB_N, 256>>>();
    k_fill<<<NB_E, 256>>>(ei);
    k_input<<<NB_W, 256>>>(x, W0, b0);

    auto cheb = [&](int k, const float* Xb, const float* resb, float* outb) {
        k_prop_csr<<<NB_W, 256>>>(Xb, pt1);
        k_prop_combine<<<NB_W, 256>>>(Xb, pt1, cW[k], cB[k], resb, outb, 1);
    };

    // block 1: h0=h; h=relu(conv11(h)); h=relu(conv12(h)+h0)
    cheb(0, ph, nullptr, pa);
    cheb(1, pa, ph,      ph);
    // block 2
    cheb(2, ph, nullptr, pa);
    cheb(3, pa, ph,      ph);

    k_final<<<NB_W, 256>>>(ph, W1, b1, out);
}

// round 8
// speedup vs baseline: 1.9008x; 1.6754x over previous
#include <cuda_runtime.h>

#define NN 200000
#define EE 3200000

// ---- device scratch (no runtime allocation allowed) ----
__device__ int      g_is64;
__device__ int      g_cnt_src[NN];
__device__ int      g_cnt_dst[NN];
__device__ int      g_fill[NN];
__device__ int      g_rowptr[NN];
__device__ float    g_dinv[NN];
__device__ unsigned g_cursor;
__device__ int2     g_pairs[EE];       // (src, w-bits) grouped contiguously by dst
__device__ float4   g_h [NN * 8];      // 32 floats per node, float4-viewed
__device__ float4   g_a [NN * 8];
__device__ float4   g_t1[NN * 8];

// ---------------------------------------------------------------- dtype detect

// Genuine int64 indices are all < NN; int32 data reinterpreted as int64 gives
// huge values almost surely. Sampled slots stay inside the buffer under either
// dtype (int32 buffer = 3.2M int64 slots; max sample 62812).
__global__ void k_detect(const void* __restrict__ eiraw) {
    const long long* p = (const long long*)eiraw;
    int ok = 1;
    for (int i = 0; i < 64; i++) {
        long long v = p[i * 997 + 1];
        if (v < 0 || v >= NN) { ok = 0; break; }
    }
    g_is64 = ok;
}

__device__ __forceinline__ void decode_edge(const void* eiraw, int e, int& s, int& d) {
    if (g_is64) {
        const long long* p = (const long long*)eiraw;
        s = (int)p[e];
        d = (int)p[EE + e];
    } else {
        const int* p = (const int*)eiraw;
        s = p[e];
        d = p[EE + e];
    }
}

// ---------------------------------------------------------------- CSR build

__global__ void k_zero() {
    int i = blockIdx.x * 256 + threadIdx.x;
    if (i < NN) { g_cnt_src[i] = 0; g_cnt_dst[i] = 0; g_fill[i] = 0; }
    if (i == 0) g_cursor = 0u;
}

__global__ void k_count(const void* __restrict__ eiraw) {
    int e = blockIdx.x * 256 + threadIdx.x;
    if (e >= EE) return;
    int s, d;
    decode_edge(eiraw, e, s, d);
    if ((unsigned)s >= NN || (unsigned)d >= NN) return;
    atomicAdd(&g_cnt_src[s], 1);
    atomicAdd(&g_cnt_dst[d], 1);
}

// dinv + contiguous row allocation (placement order irrelevant)
__global__ void k_dinv_rowalloc() {
    int i = blockIdx.x * 256 + threadIdx.x;
    if (i >= NN) return;
    int c = g_cnt_src[i];
    g_dinv[i] = (c > 0) ? rsqrtf((float)c) : 0.0f;
    g_rowptr[i] = (int)atomicAdd(&g_cursor, (unsigned)g_cnt_dst[i]);
}

__global__ void k_fill(const void* __restrict__ eiraw) {
    int e = blockIdx.x * 256 + threadIdx.x;
    if (e >= EE) return;
    int s, d;
    decode_edge(eiraw, e, s, d);
    if ((unsigned)s >= NN || (unsigned)d >= NN) return;
    float w = -g_dinv[s] * g_dinv[d];
    int pos = g_rowptr[d] + atomicAdd(&g_fill[d], 1);
    g_pairs[pos] = make_int2(s, __float_as_int(w));
}

// ---------------------------------------------------------------- input layer

// h = relu(x @ W0 + b0). 8 lanes per node, lane handles 4 output features.
__global__ void __launch_bounds__(256) k_input(const float* __restrict__ x,
                                               const float* __restrict__ W0,
                                               const float* __restrict__ b0) {
    int tid = blockIdx.x * 256 + threadIdx.x;
    int n = tid >> 3, c = tid & 7;
    if (n >= NN) return;
    float x0 = __ldg(&x[n * 3 + 0]);
    float x1 = __ldg(&x[n * 3 + 1]);
    float x2 = __ldg(&x[n * 3 + 2]);
    const float4* W04 = (const float4*)W0;
    float4 w0 = __ldg(&W04[c]);
    float4 w1 = __ldg(&W04[8 + c]);
    float4 w2 = __ldg(&W04[16 + c]);
    float4 acc = __ldg(&((const float4*)b0)[c]);
    acc.x = fmaf(x0, w0.x, fmaf(x1, w1.x, fmaf(x2, w2.x, acc.x)));
    acc.y = fmaf(x0, w0.y, fmaf(x1, w1.y, fmaf(x2, w2.y, acc.y)));
    acc.z = fmaf(x0, w0.z, fmaf(x1, w1.z, fmaf(x2, w2.z, acc.z)));
    acc.w = fmaf(x0, w0.w, fmaf(x1, w1.w, fmaf(x2, w2.w, acc.w)));
    acc.x = fmaxf(acc.x, 0.0f); acc.y = fmaxf(acc.y, 0.0f);
    acc.z = fmaxf(acc.z, 0.0f); acc.w = fmaxf(acc.w, 0.0f);
    g_h[n * 8 + c] = acc;
}

// ---------------------------------------------------------------- propagation

// Row accumulation: 8 lanes per node (lane handles 4 features via float4).
// One warp covers 4 nodes -> one warp gather-LDG.128 moves 4x128B (4 edges).
__device__ __forceinline__ float4 prop_row4(const float4* __restrict__ X,
                                            int n, int c) {
    int row = __ldg(&g_rowptr[n]);
    int deg = __ldg(&g_cnt_dst[n]);
    float4 acc = make_float4(0.f, 0.f, 0.f, 0.f);
#pragma unroll 4
    for (int k = 0; k < deg; k++) {
        int2 pr = __ldg(&g_pairs[row + k]);     // uniform within 8-lane group
        float w  = __int_as_float(pr.y);
        float4 v = __ldg(&X[pr.x * 8 + c]);     // group covers full 128B row
        acc.x = fmaf(w, v.x, acc.x);
        acc.y = fmaf(w, v.y, acc.y);
        acc.z = fmaf(w, v.z, acc.z);
        acc.w = fmaf(w, v.w, acc.w);
    }
    return acc;
}

// T1 = L~ X  (first Chebyshev propagation)
__global__ void __launch_bounds__(256) k_prop_csr(const float4* __restrict__ X,
                                                  float4* __restrict__ Y) {
    int tid = blockIdx.x * 256 + threadIdx.x;
    int n = tid >> 3, c = tid & 7;
    if (n >= NN) return;
    Y[n * 8 + c] = prop_row4(X, n, c);
}

__device__ __forceinline__ float getc(const float4& v, int comp) {
    return comp == 0 ? v.x : comp == 1 ? v.y : comp == 2 ? v.z : v.w;
}

// Second propagation fused with combine:
// y = L~ T1 ; T2 = 2y - X ; out = X@W[0] + T1@W[1] + T2@W[2] + b [+res][relu]
// Broadcasts via width-8 shfl serve all 4 node-groups of the warp at once.
__global__ void __launch_bounds__(256) k_prop_combine(const float4* __restrict__ X,
                                                      const float4* __restrict__ T1,
                                                      const float* __restrict__ W,
                                                      const float* __restrict__ bias,
                                                      const float4* __restrict__ res,
                                                      float4* __restrict__ out,
                                                      int doRelu) {
    __shared__ float4 sW[768];   // [3][32][8] float4 view of W[3][32][32]
    __shared__ float4 sB[8];
    for (int i = threadIdx.x; i < 768; i += 256) sW[i] = ((const float4*)W)[i];
    if (threadIdx.x < 8) sB[threadIdx.x] = ((const float4*)bias)[threadIdx.x];
    __syncthreads();

    int tid = blockIdx.x * 256 + threadIdx.x;
    int n = tid >> 3, c = tid & 7;
    if (n >= NN) return;

    float4 y   = prop_row4(T1, n, c);
    float4 xv  = __ldg(&X[n * 8 + c]);
    float4 t1v = __ldg(&T1[n * 8 + c]);
    float4 t2v = make_float4(2.0f * y.x - xv.x, 2.0f * y.y - xv.y,
                             2.0f * y.z - xv.z, 2.0f * y.w - xv.w);

    float4 acc = sB[c];
    if (res) {
        float4 r = __ldg(&res[n * 8 + c]);
        acc.x += r.x; acc.y += r.y; acc.z += r.z; acc.w += r.w;
    }
#pragma unroll
    for (int i = 0; i < 32; i++) {
        const int src = i >> 2, comp = i & 3;           // compile-time
        float xi = __shfl_sync(0xffffffffu, getc(xv,  comp), src, 8);
        float ai = __shfl_sync(0xffffffffu, getc(t1v, comp), src, 8);
        float ti = __shfl_sync(0xffffffffu, getc(t2v, comp), src, 8);
        float4 wx = sW[i * 8 + c];
        float4 wa = sW[256 + i * 8 + c];
        float4 wt = sW[512 + i * 8 + c];
        acc.x = fmaf(xi, wx.x, fmaf(ai, wa.x, fmaf(ti, wt.x, acc.x)));
        acc.y = fmaf(xi, wx.y, fmaf(ai, wa.y, fmaf(ti, wt.y, acc.y)));
        acc.z = fmaf(xi, wx.z, fmaf(ai, wa.z, fmaf(ti, wt.z, acc.z)));
        acc.w = fmaf(xi, wx.w, fmaf(ai, wa.w, fmaf(ti, wt.w, acc.w)));
    }
    if (doRelu) {
        acc.x = fmaxf(acc.x, 0.0f); acc.y = fmaxf(acc.y, 0.0f);
        acc.z = fmaxf(acc.z, 0.0f); acc.w = fmaxf(acc.w, 0.0f);
    }
    out[n * 8 + c] = acc;
}

// ---------------------------------------------------------------- output head

__global__ void __launch_bounds__(256) k_final(const float4* __restrict__ H,
                                               const float* __restrict__ W1,
                                               const float* __restrict__ b1,
                                               float* __restrict__ out) {
    int tid = blockIdx.x * 256 + threadIdx.x;
    int n = tid >> 3, c = tid & 7;
    if (n >= NN) return;
    float4 h = __ldg(&H[n * 8 + c]);
    float4 w = __ldg(&((const float4*)W1)[c]);
    float v = h.x * w.x + h.y * w.y + h.z * w.z + h.w * w.w;
    v += __shfl_down_sync(0xffffffffu, v, 4, 8);
    v += __shfl_down_sync(0xffffffffu, v, 2, 8);
    v += __shfl_down_sync(0xffffffffu, v, 1, 8);
    if (c == 0) out[n] = v + __ldg(b1);
}

// ---------------------------------------------------------------- launch

extern "C" void kernel_launch(void* const* d_in, const int* in_sizes, int n_in,
                              void* d_out, int out_size) {
    // ---- resolve inputs by element count (robust to metadata ordering) ----
    int idx_x = 0, idx_ei = 1, idx_W0 = 2, idx_b1 = 13;
    int chebW[4] = {4, 6, 8, 10};
    int chebB[4] = {5, 7, 9, 11};
    int idx_b0 = 3, idx_W1 = 12;
    {
        int cw[4], ncw = 0, s32[8], ns = 0;
        int ix = -1, iei = -1, iw0 = -1, ib1 = -1;
        for (int i = 0; i < n_in; i++) {
            int s = in_sizes[i];
            if (s == 600000) ix = i;
            else if (s == 6400000) iei = i;
            else if (s == 96) iw0 = i;
            else if (s == 1) ib1 = i;
            else if (s == 3072 && ncw < 4) cw[ncw++] = i;
            else if (s == 32 && ns < 8) s32[ns++] = i;
        }
        if (ix >= 0 && iei >= 0 && iw0 >= 0 && ib1 >= 0 && ncw == 4 && ns == 6) {
            idx_x = ix; idx_ei = iei; idx_W0 = iw0; idx_b1 = ib1;
            int rem[2], nr = 0;
            for (int k = 0; k < 4; k++) chebW[k] = cw[k];
            for (int i = 0; i < 6; i++) {
                int isb = 0;
                for (int k = 0; k < 4; k++)
                    if (s32[i] == cw[k] + 1) { chebB[k] = s32[i]; isb = 1; }
                if (!isb && nr < 2) rem[nr++] = s32[i];
            }
            if (nr == 2) {
                if (rem[1] == rem[0] + 1) { idx_W1 = rem[0]; idx_b0 = rem[1]; }
                else                      { idx_b0 = rem[0]; idx_W1 = rem[1]; }
            }
        }
    }

    const float* x    = (const float*)d_in[idx_x];
    const void*  ei   = d_in[idx_ei];
    const float* W0   = (const float*)d_in[idx_W0];
    const float* b0   = (const float*)d_in[idx_b0];
    const float* cW[4], *cB[4];
    for (int k = 0; k < 4; k++) { cW[k] = (const float*)d_in[chebW[k]]; cB[k] = (const float*)d_in[chebB[k]]; }
    const float* W1   = (const float*)d_in[idx_W1];
    const float* b1   = (const float*)d_in[idx_b1];
    float*       out  = (float*)d_out;

    float4 *ph, *pa, *pt1;
    cudaGetSymbolAddress((void**)&ph,  g_h);
    cudaGetSymbolAddress((void**)&pa,  g_a);
    cudaGetSymbolAddress((void**)&pt1, g_t1);

    const int NB_N = (NN + 255) / 256;
    const int NB_E = (EE + 255) / 256;
    const int NB_8 = (NN * 8) / 256;     // 6250 blocks: 8 threads per node

    k_detect<<<1, 1>>>(ei);
    k_zero<<<NB_N, 256>>>();
    k_count<<<NB_E, 256>>>(ei);
    k_dinv_rowalloc<<<NB_N, 256>>>();
    k_fill<<<NB_E, 256>>>(ei);
    k_input<<<NB_8, 256>>>(x, W0, b0);

    auto cheb = [&](int k, const float4* Xb, const float4* resb, float4* outb) {
        k_prop_csr<<<NB_8, 256>>>(Xb, pt1);
        k_prop_combine<<<NB_8, 256>>>(Xb, pt1, cW[k], cB[k], resb, outb, 1);
    };

    // block 1: h0=h; h=relu(conv11(h)); h=relu(conv12(h)+h0)
    cheb(0, ph, nullptr, pa);
    cheb(1, pa, ph,      ph);
    // block 2
    cheb(2, ph, nullptr, pa);
    cheb(3, pa, ph,      ph);

    k_final<<<NB_8, 256>>>(ph, W1, b1, out);
}

// round 9
// speedup vs baseline: 1.9023x; 1.0008x over previous
#include <cuda_runtime.h>

#define NN 200000
#define EE 3200000
#define NBIN 1024

// ---- device scratch (no runtime allocation allowed) ----
__device__ int      g_is64;
__device__ int      g_cnt_src[NN];
__device__ int      g_cnt_dst[NN];
__device__ int      g_fill[NN];
__device__ int      g_rowptr[NN];
__device__ float    g_dinv[NN];
__device__ int      g_hist[NBIN];
__device__ int      g_cur[NBIN];
__device__ int      g_rank_base[NBIN];
__device__ int      g_edge_base[NBIN];
__device__ int      g_ovf_cursor;
__device__ int      g_srt_node[NN];     // rank -> node
__device__ int2     g_srt_rowdeg[NN];   // rank -> (row, deg)
__device__ int2     g_pairs[EE];        // (src, w-bits) grouped contiguously by dst
__device__ float4   g_h [NN * 8];       // 32 floats per node, float4-viewed
__device__ float4   g_a [NN * 8];
__device__ float4   g_t1[NN * 8];

// ---------------------------------------------------------------- dtype detect

// Genuine int64 indices are all < NN; int32 data reinterpreted as int64 gives
// huge values almost surely. Sampled slots stay inside the buffer under either
// dtype (int32 buffer = 3.2M int64 slots; max sample 62812).
__global__ void k_detect(const void* __restrict__ eiraw) {
    const long long* p = (const long long*)eiraw;
    int ok = 1;
    for (int i = 0; i < 64; i++) {
        long long v = p[i * 997 + 1];
        if (v < 0 || v >= NN) { ok = 0; break; }
    }
    g_is64 = ok;
}

__device__ __forceinline__ void decode_edge(const void* eiraw, int e, int& s, int& d) {
    if (g_is64) {
        const long long* p = (const long long*)eiraw;
        s = (int)p[e];
        d = (int)p[EE + e];
    } else {
        const int* p = (const int*)eiraw;
        s = p[e];
        d = p[EE + e];
    }
}

// ---------------------------------------------------------------- CSR build

__global__ void k_zero() {
    int i = blockIdx.x * 256 + threadIdx.x;
    if (i < NN) { g_cnt_src[i] = 0; g_cnt_dst[i] = 0; g_fill[i] = 0; }
    if (i < NBIN) { g_hist[i] = 0; g_cur[i] = 0; }
}

__global__ void k_count(const void* __restrict__ eiraw) {
    int e = blockIdx.x * 256 + threadIdx.x;
    if (e >= EE) return;
    int s, d;
    decode_edge(eiraw, e, s, d);
    if ((unsigned)s >= NN || (unsigned)d >= NN) return;
    atomicAdd(&g_cnt_src[s], 1);
    atomicAdd(&g_cnt_dst[d], 1);
}

// histogram of in-degrees (block-local smem, then merge)
__global__ void __launch_bounds__(256) k_hist() {
    __shared__ int sh[NBIN];
    for (int i = threadIdx.x; i < NBIN; i += 256) sh[i] = 0;
    __syncthreads();
    int i = blockIdx.x * 256 + threadIdx.x;
    if (i < NN) {
        int b = g_cnt_dst[i]; if (b > NBIN - 1) b = NBIN - 1;
        atomicAdd(&sh[b], 1);
    }
    __syncthreads();
    for (int b = threadIdx.x; b < NBIN; b += 256)
        if (sh[b]) atomicAdd(&g_hist[b], sh[b]);
}

// exclusive prefixes over bins: rank_base (nodes), edge_base (edges)
__global__ void __launch_bounds__(NBIN) k_scan() {
    __shared__ int sh[NBIN];
    __shared__ long long se[NBIN];
    int t = threadIdx.x;
    int h = g_hist[t];
    sh[t] = h;
    se[t] = (long long)h * t;
    __syncthreads();
    for (int o = 1; o < NBIN; o <<= 1) {
        int a = 0; long long b = 0;
        if (t >= o) { a = sh[t - o]; b = se[t - o]; }
        __syncthreads();
        sh[t] += a; se[t] += b;
        __syncthreads();
    }
    g_rank_base[t] = sh[t] - h;
    g_edge_base[t] = (int)(se[t] - (long long)h * t);
    if (t == NBIN - 1) g_ovf_cursor = (int)(se[t] - (long long)h * t);
}

// per-node: dinv, degree-sorted rank, and arithmetic row allocation
__global__ void k_rank() {
    int i = blockIdx.x * 256 + threadIdx.x;
    if (i >= NN) return;
    int cs = g_cnt_src[i];
    g_dinv[i] = (cs > 0) ? rsqrtf((float)cs) : 0.0f;
    int deg = g_cnt_dst[i];
    int bin = (deg > NBIN - 1) ? NBIN - 1 : deg;
    int off = atomicAdd(&g_cur[bin], 1);
    int r = g_rank_base[bin] + off;
    int row;
    if (bin < NBIN - 1) row = g_edge_base[bin] + off * deg;
    else                row = atomicAdd(&g_ovf_cursor, deg);   // never in practice
    g_rowptr[i] = row;
    g_srt_node[r] = i;
    g_srt_rowdeg[r] = make_int2(row, deg);
}

__global__ void k_fill(const void* __restrict__ eiraw) {
    int e = blockIdx.x * 256 + threadIdx.x;
    if (e >= EE) return;
    int s, d;
    decode_edge(eiraw, e, s, d);
    if ((unsigned)s >= NN || (unsigned)d >= NN) return;
    float w = -g_dinv[s] * g_dinv[d];
    int pos = g_rowptr[d] + atomicAdd(&g_fill[d], 1);
    g_pairs[pos] = make_int2(s, __float_as_int(w));
}

// ---------------------------------------------------------------- input layer

// h = relu(x @ W0 + b0). 8 lanes per node, lane handles 4 output features.
__global__ void __launch_bounds__(256) k_input(const float* __restrict__ x,
                                               const float* __restrict__ W0,
                                               const float* __restrict__ b0) {
    int tid = blockIdx.x * 256 + threadIdx.x;
    int n = tid >> 3, c = tid & 7;
    if (n >= NN) return;
    float x0 = __ldg(&x[n * 3 + 0]);
    float x1 = __ldg(&x[n * 3 + 1]);
    float x2 = __ldg(&x[n * 3 + 2]);
    const float4* W04 = (const float4*)W0;
    float4 w0 = __ldg(&W04[c]);
    float4 w1 = __ldg(&W04[8 + c]);
    float4 w2 = __ldg(&W04[16 + c]);
    float4 acc = __ldg(&((const float4*)b0)[c]);
    acc.x = fmaf(x0, w0.x, fmaf(x1, w1.x, fmaf(x2, w2.x, acc.x)));
    acc.y = fmaf(x0, w0.y, fmaf(x1, w1.y, fmaf(x2, w2.y, acc.y)));
    acc.z = fmaf(x0, w0.z, fmaf(x1, w1.z, fmaf(x2, w2.z, acc.z)));
    acc.w = fmaf(x0, w0.w, fmaf(x1, w1.w, fmaf(x2, w2.w, acc.w)));
    acc.x = fmaxf(acc.x, 0.0f); acc.y = fmaxf(acc.y, 0.0f);
    acc.z = fmaxf(acc.z, 0.0f); acc.w = fmaxf(acc.w, 0.0f);
    g_h[n * 8 + c] = acc;
}

// ---------------------------------------------------------------- propagation

// Row accumulation: 8 lanes per node (lane handles 4 features via float4).
// One warp covers 4 equal-degree nodes (degree-sorted) -> balanced loop.
__device__ __forceinline__ float4 prop_row4(const float4* __restrict__ X,
                                            int row, int deg, int c) {
    float4 acc = make_float4(0.f, 0.f, 0.f, 0.f);
#pragma unroll 4
    for (int k = 0; k < deg; k++) {
        int2 pr = __ldg(&g_pairs[row + k]);     // uniform within 8-lane group
        float w  = __int_as_float(pr.y);
        float4 v = __ldg(&X[pr.x * 8 + c]);     // group covers full 128B row
        acc.x = fmaf(w, v.x, acc.x);
        acc.y = fmaf(w, v.y, acc.y);
        acc.z = fmaf(w, v.z, acc.z);
        acc.w = fmaf(w, v.w, acc.w);
    }
    return acc;
}

// T1 = L~ X  (first Chebyshev propagation), rank-ordered for warp balance
__global__ void __launch_bounds__(256) k_prop_csr(const float4* __restrict__ X,
                                                  float4* __restrict__ Y) {
    int tid = blockIdx.x * 256 + threadIdx.x;
    int r = tid >> 3, c = tid & 7;
    if (r >= NN) return;
    int n  = __ldg(&g_srt_node[r]);
    int2 rd = __ldg(&g_srt_rowdeg[r]);
    Y[n * 8 + c] = prop_row4(X, rd.x, rd.y, c);
}

__device__ __forceinline__ float getc(const float4& v, int comp) {
    return comp == 0 ? v.x : comp == 1 ? v.y : comp == 2 ? v.z : v.w;
}

// Second propagation fused with combine:
// y = L~ T1 ; T2 = 2y - X ; out = X@W[0] + T1@W[1] + T2@W[2] + b [+res][relu]
// Broadcasts via width-8 shfl serve all 4 node-groups of the warp at once.
__global__ void __launch_bounds__(256) k_prop_combine(const float4* __restrict__ X,
                                                      const float4* __restrict__ T1,
                                                      const float* __restrict__ W,
                                                      const float* __restrict__ bias,
                                                      const float4* __restrict__ res,
                                                      float4* __restrict__ out,
                                                      int doRelu) {
    __shared__ float4 sW[768];   // [3][32][8] float4 view of W[3][32][32]
    __shared__ float4 sB[8];
    for (int i = threadIdx.x; i < 768; i += 256) sW[i] = ((const float4*)W)[i];
    if (threadIdx.x < 8) sB[threadIdx.x] = ((const float4*)bias)[threadIdx.x];
    __syncthreads();

    int tid = blockIdx.x * 256 + threadIdx.x;
    int r = tid >> 3, c = tid & 7;
    if (r >= NN) return;
    int n  = __ldg(&g_srt_node[r]);
    int2 rd = __ldg(&g_srt_rowdeg[r]);

    float4 y   = prop_row4(T1, rd.x, rd.y, c);
    float4 xv  = __ldg(&X[n * 8 + c]);
    float4 t1v = __ldg(&T1[n * 8 + c]);
    float4 t2v = make_float4(2.0f * y.x - xv.x, 2.0f * y.y - xv.y,
                             2.0f * y.z - xv.z, 2.0f * y.w - xv.w);

    float4 acc = sB[c];
    if (res) {
        float4 rr = __ldg(&res[n * 8 + c]);
        acc.x += rr.x; acc.y += rr.y; acc.z += rr.z; acc.w += rr.w;
    }
#pragma unroll
    for (int i = 0; i < 32; i++) {
        const int src = i >> 2, comp = i & 3;           // compile-time
        float xi = __shfl_sync(0xffffffffu, getc(xv,  comp), src, 8);
        float ai = __shfl_sync(0xffffffffu, getc(t1v, comp), src, 8);
        float ti = __shfl_sync(0xffffffffu, getc(t2v, comp), src, 8);
        float4 wx = sW[i * 8 + c];
        float4 wa = sW[256 + i * 8 + c];
        float4 wt = sW[512 + i * 8 + c];
        acc.x = fmaf(xi, wx.x, fmaf(ai, wa.x, fmaf(ti, wt.x, acc.x)));
        acc.y = fmaf(xi, wx.y, fmaf(ai, wa.y, fmaf(ti, wt.y, acc.y)));
        acc.z = fmaf(xi, wx.z, fmaf(ai, wa.z, fmaf(ti, wt.z, acc.z)));
        acc.w = fmaf(xi, wx.w, fmaf(ai, wa.w, fmaf(ti, wt.w, acc.w)));
    }
    if (doRelu) {
        acc.x = fmaxf(acc.x, 0.0f); acc.y = fmaxf(acc.y, 0.0f);
        acc.z = fmaxf(acc.z, 0.0f); acc.w = fmaxf(acc.w, 0.0f);
    }
    out[n * 8 + c] = acc;
}

// ---------------------------------------------------------------- output head

__global__ void __launch_bounds__(256) k_final(const float4* __restrict__ H,
                                               const float* __restrict__ W1,
                                               const float* __restrict__ b1,
                                               float* __restrict__ out) {
    int tid = blockIdx.x * 256 + threadIdx.x;
    int n = tid >> 3, c = tid & 7;
    if (n >= NN) return;
    float4 h = __ldg(&H[n * 8 + c]);
    float4 w = __ldg(&((const float4*)W1)[c]);
    float v = h.x * w.x + h.y * w.y + h.z * w.z + h.w * w.w;
    v += __shfl_down_sync(0xffffffffu, v, 4, 8);
    v += __shfl_down_sync(0xffffffffu, v, 2, 8);
    v += __shfl_down_sync(0xffffffffu, v, 1, 8);
    if (c == 0) out[n] = v + __ldg(b1);
}

// ---------------------------------------------------------------- launch

extern "C" void kernel_launch(void* const* d_in, const int* in_sizes, int n_in,
                              void* d_out, int out_size) {
    // ---- resolve inputs by element count (robust to metadata ordering) ----
    int idx_x = 0, idx_ei = 1, idx_W0 = 2, idx_b1 = 13;
    int chebW[4] = {4, 6, 8, 10};
    int chebB[4] = {5, 7, 9, 11};
    int idx_b0 = 3, idx_W1 = 12;
    {
        int cw[4], ncw = 0, s32[8], ns = 0;
        int ix = -1, iei = -1, iw0 = -1, ib1 = -1;
        for (int i = 0; i < n_in; i++) {
            int s = in_sizes[i];
            if (s == 600000) ix = i;
            else if (s == 6400000) iei = i;
            else if (s == 96) iw0 = i;
            else if (s == 1) ib1 = i;
            else if (s == 3072 && ncw < 4) cw[ncw++] = i;
            else if (s == 32 && ns < 8) s32[ns++] = i;
        }
        if (ix >= 0 && iei >= 0 && iw0 >= 0 && ib1 >= 0 && ncw == 4 && ns == 6) {
            idx_x = ix; idx_ei = iei; idx_W0 = iw0; idx_b1 = ib1;
            int rem[2], nr = 0;
            for (int k = 0; k < 4; k++) chebW[k] = cw[k];
            for (int i = 0; i < 6; i++) {
                int isb = 0;
                for (int k = 0; k < 4; k++)
                    if (s32[i] == cw[k] + 1) { chebB[k] = s32[i]; isb = 1; }
                if (!isb && nr < 2) rem[nr++] = s32[i];
            }
            if (nr == 2) {
                if (rem[1] == rem[0] + 1) { idx_W1 = rem[0]; idx_b0 = rem[1]; }
                else                      { idx_b0 = rem[0]; idx_W1 = rem[1]; }
            }
        }
    }

    const float* x    = (const float*)d_in[idx_x];
    const void*  ei   = d_in[idx_ei];
    const float* W0   = (const float*)d_in[idx_W0];
    const float* b0   = (const float*)d_in[idx_b0];
    const float* cW[4], *cB[4];
    for (int k = 0; k < 4; k++) { cW[k] = (const float*)d_in[chebW[k]]; cB[k] = (const float*)d_in[chebB[k]]; }
    const float* W1   = (const float*)d_in[idx_W1];
    const float* b1   = (const float*)d_in[idx_b1];
    float*       out  = (float*)d_out;

    float4 *ph, *pa, *pt1;
    cudaGetSymbolAddress((void**)&ph,  g_h);
    cudaGetSymbolAddress((void**)&pa,  g_a);
    cudaGetSymbolAddress((void**)&pt1, g_t1);

    const int NB_N = (NN + 255) / 256;
    const int NB_E = (EE + 255) / 256;
    const int NB_8 = (NN * 8) / 256;     // 6250 blocks: 8 threads per node

    k_detect<<<1, 1>>>(ei);
    k_zero<<<NB_N, 256>>>();
    k_count<<<NB_E, 256>>>(ei);
    k_hist<<<NB_N, 256>>>();
    k_scan<<<1, NBIN>>>();
    k_rank<<<NB_N, 256>>>();
    k_fill<<<NB_E, 256>>>(ei);
    k_input<<<NB_8, 256>>>(x, W0, b0);

    auto cheb = [&](int k, const float4* Xb, const float4* resb, float4* outb) {
        k_prop_csr<<<NB_8, 256>>>(Xb, pt1);
        k_prop_combine<<<NB_8, 256>>>(Xb, pt1, cW[k], cB[k], resb, outb, 1);
    };

    // block 1: h0=h; h=relu(conv11(h)); h=relu(conv12(h)+h0)
    cheb(0, ph, nullptr, pa);
    cheb(1, pa, ph,      ph);
    // block 2
    cheb(2, ph, nullptr, pa);
    cheb(3, pa, ph,      ph);

    k_final<<<NB_8, 256>>>(ph, W1, b1, out);
}